// round 9
// baseline (speedup 1.0000x reference)
#include <cuda_runtime.h>

#define NN 50000
#define NE 1600000
#define NF 1433
#define NH 256
#define NC 7

// ------------------- scratch (static device globals; no runtime alloc) ----
__device__ int   g_cnt[NN];
__device__ int   g_rowptr[NN + 1];
__device__ int   g_cur[NN];
__device__ float g_dinv[NN];
__device__ int   g_col[NE];
__device__ int   g_is64;                  // 1 if edge_index is int64, else int32
__device__ float g_h [(size_t)NN * NH];   // x @ W1
__device__ float g_h1[(size_t)NN * NH];   // relu(agg1 + b1)
__device__ float g_g [NN * 8];            // h1 @ W2, padded stride 8

// ------------------- dtype detection --------------------------------------
// int64 little-endian layout: odd 32-bit words of the first values are the
// high halves of indices < 2^31  => all zero. int32 layout: random node ids.
__global__ void detect_kernel(const int* __restrict__ ei32) {
    if (threadIdx.x == 0 && blockIdx.x == 0) {
        int flag = 1;
        for (int i = 1; i < 200; i += 2)
            if (ei32[i] != 0) { flag = 0; break; }
        g_is64 = flag;
    }
}

__device__ __forceinline__ int edge_src(const int* ei32, int e) {
    return g_is64 ? ei32[2 * (size_t)e] : ei32[e];
}
__device__ __forceinline__ int edge_dst(const int* ei32, int e) {
    return g_is64 ? ei32[2 * ((size_t)NE + e)] : ei32[NE + e];
}

// ------------------- graph preprocessing ----------------------------------
__global__ void zero_cnt_kernel() {
    int i = blockIdx.x * blockDim.x + threadIdx.x;
    if (i < NN) g_cnt[i] = 0;
}

__global__ void count_kernel(const int* __restrict__ ei32) {
    int e = blockIdx.x * blockDim.x + threadIdx.x;
    if (e < NE) {
        int d = edge_dst(ei32, e);
        if ((unsigned)d < NN) atomicAdd(&g_cnt[d], 1);
    }
}

// single-block prefix scan over 50000 counts; also dinv = rsqrt(deg_in + 1)
__global__ void scan_kernel() {
    __shared__ int warp_sums[32];
    __shared__ int s_carry;
    const int tid  = threadIdx.x;          // 1024 threads
    const int lane = tid & 31, wid = tid >> 5;
    if (tid == 0) s_carry = 0;
    __syncthreads();
    for (int base = 0; base < NN; base += 1024) {
        int i = base + tid;
        int v = (i < NN) ? g_cnt[i] : 0;
        int x = v;
        #pragma unroll
        for (int o = 1; o < 32; o <<= 1) {
            int t = __shfl_up_sync(0xffffffffu, x, o);
            if (lane >= o) x += t;
        }
        if (lane == 31) warp_sums[wid] = x;
        __syncthreads();
        if (tid < 32) {
            int y = warp_sums[tid];
            #pragma unroll
            for (int o = 1; o < 32; o <<= 1) {
                int t = __shfl_up_sync(0xffffffffu, y, o);
                if (tid >= o) y += t;
            }
            warp_sums[tid] = y;
        }
        __syncthreads();
        int incl = x + (wid ? warp_sums[wid - 1] : 0);
        int excl = incl - v + s_carry;
        if (i < NN) {
            g_rowptr[i] = excl;
            g_cur[i]    = excl;
            g_dinv[i]   = rsqrtf((float)(v + 1));   // +1 = self loop
        }
        __syncthreads();
        if (tid == 1023) s_carry += incl;
        __syncthreads();
    }
    if (tid == 0) g_rowptr[NN] = s_carry;
}

__global__ void fill_kernel(const int* __restrict__ ei32) {
    int e = blockIdx.x * blockDim.x + threadIdx.x;
    if (e < NE) {
        int s = edge_src(ei32, e);
        int d = edge_dst(ei32, e);
        if ((unsigned)s < NN && (unsigned)d < NN) {
            int p = atomicAdd(&g_cur[d], 1);
            if ((unsigned)p < NE) g_col[p] = s;
        }
    }
}

// ------------------- GEMM1: g_h = x[NN,NF] @ W1[NF,NH] ---------------------
// 128x128 tile / CTA, BK=16, single-buffer, scalar FFMA, aligned float4 LDS.
__global__ void __launch_bounds__(256, 2) gemm1_kernel(const float* __restrict__ A,
                                                       const float* __restrict__ B) {
    __shared__ __align__(16) float As[16][132];   // As[k][m]
    __shared__ __align__(16) float Bs[16][132];   // Bs[k][n]
    const int tid  = threadIdx.x;
    const int tx   = tid & 15;     // A-load k index / compute n-group
    const int ty   = tid >> 4;     // A-load m base  / compute m-group
    const int row0 = blockIdx.x * 128;
    const int col0 = blockIdx.y * 128;

    const int bk  = tid >> 5;      // 0..7  (B-load k base)
    const int bn4 = tid & 31;      // B-load n/4 index

    float acc[8][8];
    #pragma unroll
    for (int i = 0; i < 8; i++)
        #pragma unroll
        for (int j = 0; j < 8; j++) acc[i][j] = 0.f;

    const int nT = (NF + 15) / 16;  // 90

    for (int t = 0; t < nT; t++) {
        const int k0 = t * 16;
        // ---- load A tile (scalar; NF=1433 row stride not 16B aligned) -----
        #pragma unroll
        for (int i = 0; i < 8; i++) {
            int r = row0 + ty + 16 * i;
            int k = k0 + tx;
            As[tx][ty + 16 * i] = (r < NN && k < NF) ? A[(size_t)r * NF + k] : 0.f;
        }
        // ---- load B tile (row stride 256 floats -> float4 safe) -----------
        #pragma unroll
        for (int i = 0; i < 2; i++) {
            int k = k0 + bk + 8 * i;
            float4 v = (k < NF) ? *(const float4*)&B[(size_t)k * NH + col0 + bn4 * 4]
                                : make_float4(0.f, 0.f, 0.f, 0.f);
            *(float4*)&Bs[bk + 8 * i][bn4 * 4] = v;
        }
        __syncthreads();

        #pragma unroll
        for (int k = 0; k < 16; k++) {
            float4 a0 = *(const float4*)&As[k][ty * 8];
            float4 a1 = *(const float4*)&As[k][ty * 8 + 4];
            float4 b0 = *(const float4*)&Bs[k][tx * 8];
            float4 b1 = *(const float4*)&Bs[k][tx * 8 + 4];
            float a[8] = {a0.x, a0.y, a0.z, a0.w, a1.x, a1.y, a1.z, a1.w};
            float b[8] = {b0.x, b0.y, b0.z, b0.w, b1.x, b1.y, b1.z, b1.w};
            #pragma unroll
            for (int i = 0; i < 8; i++)
                #pragma unroll
                for (int j = 0; j < 8; j++)
                    acc[i][j] = fmaf(a[i], b[j], acc[i][j]);
        }
        __syncthreads();
    }

    #pragma unroll
    for (int i = 0; i < 8; i++) {
        int r = row0 + ty * 8 + i;
        if (r < NN) {
            float* dst = &g_h[(size_t)r * NH + col0 + tx * 8];
            *(float4*)dst       = make_float4(acc[i][0], acc[i][1], acc[i][2], acc[i][3]);
            *(float4*)(dst + 4) = make_float4(acc[i][4], acc[i][5], acc[i][6], acc[i][7]);
        }
    }
}

// ------------------- aggregation layer 1 (CSR gather, no atomics) ----------
// h1[i] = relu( dinv[i] * sum_{s in N(i)} dinv[s]*h[s] + dinv[i]^2*h[i] + b1 )
__global__ void agg1_kernel(const float* __restrict__ b1) {
    __shared__ int   scol[128];
    __shared__ float snrm[128];
    const int i = blockIdx.x;
    const int f = threadIdx.x;   // 256 = NH
    const int start = g_rowptr[i];
    const int end   = g_rowptr[i + 1];
    float acc = 0.f;
    for (int p0 = start; p0 < end; p0 += 128) {
        int n = min(128, end - p0);
        if (f < n) {
            int s = g_col[p0 + f];
            scol[f] = s;
            snrm[f] = g_dinv[s];
        }
        __syncthreads();
        int j = 0;
        for (; j + 4 <= n; j += 4) {
            int s0 = scol[j], s1 = scol[j + 1], s2 = scol[j + 2], s3 = scol[j + 3];
            float w0 = snrm[j], w1 = snrm[j + 1], w2 = snrm[j + 2], w3 = snrm[j + 3];
            float h0  = g_h[(size_t)s0 * NH + f];
            float h1v = g_h[(size_t)s1 * NH + f];
            float h2  = g_h[(size_t)s2 * NH + f];
            float h3  = g_h[(size_t)s3 * NH + f];
            acc = fmaf(w0, h0, acc);
            acc = fmaf(w1, h1v, acc);
            acc = fmaf(w2, h2, acc);
            acc = fmaf(w3, h3, acc);
        }
        for (; j < n; j++)
            acc = fmaf(snrm[j], g_h[(size_t)scol[j] * NH + f], acc);
        __syncthreads();
    }
    float di = g_dinv[i];
    float v  = fmaf(di, acc, di * di * g_h[(size_t)i * NH + f]) + b1[f];
    g_h1[(size_t)i * NH + f] = fmaxf(v, 0.f);
}

// ------------------- GEMM2: g_g = h1[NN,256] @ W2[256,7] -------------------
__global__ void gemm2_kernel(const float* __restrict__ W2) {
    __shared__ float sW[NH * NC];
    const int tid = threadIdx.x;   // 256 threads, 8 warps, 1 node/warp
    for (int t = tid; t < NH * NC; t += 256) sW[t] = W2[t];
    __syncthreads();
    const int lane = tid & 31;
    const int node = blockIdx.x * 8 + (tid >> 5);
    float p[NC];
    #pragma unroll
    for (int j = 0; j < NC; j++) p[j] = 0.f;
    #pragma unroll
    for (int u = 0; u < 8; u++) {
        int k = u * 32 + lane;
        float v = g_h1[(size_t)node * NH + k];
        #pragma unroll
        for (int j = 0; j < NC; j++) p[j] = fmaf(v, sW[k * NC + j], p[j]);
    }
    #pragma unroll
    for (int o = 16; o > 0; o >>= 1)
        #pragma unroll
        for (int j = 0; j < NC; j++) p[j] += __shfl_down_sync(0xffffffffu, p[j], o);
    if (lane == 0) {
        #pragma unroll
        for (int j = 0; j < NC; j++) g_g[node * 8 + j] = p[j];
        g_g[node * 8 + 7] = 0.f;
    }
}

// ------------------- aggregation layer 2 (7-wide, CSR gather) --------------
__global__ void agg2_kernel(const float* __restrict__ b2, float* __restrict__ out) {
    const int tid  = threadIdx.x;            // 256 = 32 nodes x 8 threads
    const int node = blockIdx.x * 32 + (tid >> 3);
    const int j    = tid & 7;
    if (node >= NN) return;
    const int start = g_rowptr[node], end = g_rowptr[node + 1];
    float acc = 0.f;
    for (int p = start; p < end; p++) {
        int s = g_col[p];
        acc = fmaf(g_dinv[s], g_g[s * 8 + j], acc);
    }
    float di = g_dinv[node];
    float v  = fmaf(di, acc, di * di * g_g[node * 8 + j]);
    if (j < NC) out[node * NC + j] = v + b2[j];
}

// ------------------- launch -----------------------------------------------
extern "C" void kernel_launch(void* const* d_in, const int* in_sizes, int n_in,
                              void* d_out, int out_size) {
    const float* x    = (const float*)d_in[0];
    const int*   ei32 = (const int*)d_in[1];   // int32 OR int64 (auto-detected)
    const float* W1   = (const float*)d_in[2];
    const float* b1   = (const float*)d_in[3];
    const float* W2   = (const float*)d_in[4];
    const float* b2   = (const float*)d_in[5];
    float*       out  = (float*)d_out;

    detect_kernel<<<1, 32>>>(ei32);
    zero_cnt_kernel<<<(NN + 255) / 256, 256>>>();
    count_kernel<<<(NE + 255) / 256, 256>>>(ei32);
    scan_kernel<<<1, 1024>>>();
    fill_kernel<<<(NE + 255) / 256, 256>>>(ei32);

    dim3 g1((NN + 127) / 128, NH / 128);
    gemm1_kernel<<<g1, 256>>>(x, W1);

    agg1_kernel<<<NN, 256>>>(b1);
    gemm2_kernel<<<NN / 8, 256>>>(W2);
    agg2_kernel<<<(NN + 31) / 32, 256>>>(b2, out);
}